// round 4
// baseline (speedup 1.0000x reference)
#include <cuda_runtime.h>
#include <cuda_bf16.h>
#include <math.h>
#include <stdint.h>

// ---------------------------------------------------------------------------
// TreeLSTM on GB300 via mma.sync bf16x3 (tcgen05 feature-gated off by the
// harness's compute_103 PTX target).
// R4: level GEMM fuses the LSTM cell in its epilogue (gate-permuted weights,
// N-tile = 160 = 32 hidden units x 5 gates); h carried as bf16 hi/lo so the
// level GEMM A-operand loads are pure cp.async; 3-stage pipeline.
// ---------------------------------------------------------------------------

#define Hc      128
#define MAXBL   32768
#define NGATE   640
#define KB_LEAF 320

__device__ __align__(128) __nv_bfloat16 g_hhiA[MAXBL * Hc];
__device__ __align__(128) __nv_bfloat16 g_hloA[MAXBL * Hc];
__device__ __align__(128) __nv_bfloat16 g_hhiB[(MAXBL / 2) * Hc];
__device__ __align__(128) __nv_bfloat16 g_hloB[(MAXBL / 2) * Hc];
__device__ float g_cA[MAXBL * Hc];
__device__ float g_cB[(MAXBL / 2) * Hc];
__device__ __align__(128) __nv_bfloat16 g_Wt_hi[NGATE * 256];     // permuted [640,256]
__device__ __align__(128) __nv_bfloat16 g_Wt_lo[NGATE * 256];
__device__ float g_bperm[NGATE];
__device__ __align__(128) __nv_bfloat16 g_WlfT_hi[256 * KB_LEAF]; // [256,320]
__device__ __align__(128) __nv_bfloat16 g_WlfT_lo[256 * KB_LEAF];

// ------------------------------- helpers -----------------------------------
__device__ __forceinline__ uint32_t smem_u32(const void* p) {
    uint32_t a;
    asm("{ .reg .u64 t; cvta.to.shared.u64 t, %1; cvt.u32.u64 %0, t; }"
        : "=r"(a) : "l"(p));
    return a;
}
#define CP_ASYNC16(dst, src) \
    asm volatile("cp.async.cg.shared.global [%0], [%1], 16;" \
                 :: "r"(dst), "l"(src) : "memory")
#define CP_COMMIT() asm volatile("cp.async.commit_group;" ::: "memory")
#define CP_WAIT1()  asm volatile("cp.async.wait_group 1;"  ::: "memory")
#define CP_WAIT0()  asm volatile("cp.async.wait_group 0;"  ::: "memory")

#define MMA16816(c, a, b)                                                      \
    asm volatile("mma.sync.aligned.m16n8k16.row.col.f32.bf16.bf16.f32 "       \
        "{%0,%1,%2,%3},{%4,%5,%6,%7},{%8,%9},{%0,%1,%2,%3};"                  \
        : "+f"((c)[0]), "+f"((c)[1]), "+f"((c)[2]), "+f"((c)[3])              \
        : "r"((a)[0]), "r"((a)[1]), "r"((a)[2]), "r"((a)[3]),                 \
          "r"((b)[0]), "r"((b)[1]))

__device__ __forceinline__ void split_bf16(float w, __nv_bfloat16* hi, __nv_bfloat16* lo) {
    __nv_bfloat16 h = __float2bfloat16(w);
    *hi = h;
    *lo = __float2bfloat16(w - __bfloat162float(h));
}
__device__ __forceinline__ uint32_t pack_bf(__nv_bfloat16 a, __nv_bfloat16 b) {
    __nv_bfloat162 t{a, b};
    return *(uint32_t*)&t;
}
__device__ __forceinline__ float sigf(float x) { return 1.0f / (1.0f + expf(-x)); }

// ------------------------ weight prep (once/replay) ------------------------
// Permutation: tile t = p/160, c = p%160; gate = c/32, unit = 32t + (c%32);
// original col n = 128*gate + unit.
__global__ void prep_wst(const float* __restrict__ Wl, const float* __restrict__ Wr,
                         const float* __restrict__ bg,
                         __nv_bfloat16* __restrict__ hi, __nv_bfloat16* __restrict__ lo,
                         float* __restrict__ bperm)
{
    int idx = blockIdx.x * blockDim.x + threadIdx.x;
    if (idx >= NGATE * 256) return;
    int p = idx >> 8, k = idx & 255;
    int t = p / 160, c = p % 160;
    int n = 128 * (c >> 5) + 32 * t + (c & 31);
    float w = (k < 128) ? Wl[k * NGATE + n] : Wr[(k - 128) * NGATE + n];
    split_bf16(w, &hi[idx], &lo[idx]);
    if (k == 0) bperm[p] = bg[n];
}

__global__ void prep_wleaf(const float* __restrict__ W,
                           __nv_bfloat16* __restrict__ hi, __nv_bfloat16* __restrict__ lo)
{
    int idx = blockIdx.x * blockDim.x + threadIdx.x;
    if (idx >= 256 * KB_LEAF) return;
    int n = idx / KB_LEAF, k = idx % KB_LEAF;
    float w = (k < 300) ? W[k * 256 + n] : 0.0f;
    split_bf16(w, &hi[idx], &lo[idx]);
}

// ------------------------------ leaf GEMM -----------------------------------
// hc = x @ W_leaf + b_leaf.  ny==0 tile -> h (split hi/lo bf16); ny==1 -> c f32.
#define ST_ROW   80
#define MAT_B    10240
#define STAGE_B  (4 * MAT_B)
#define SMEM_LEAF (2 * STAGE_B)

__global__ void __launch_bounds__(256, 1)
gemm_leaf(const float* __restrict__ A,
          const __nv_bfloat16* __restrict__ Bhi, const __nv_bfloat16* __restrict__ Blo,
          const float* __restrict__ bias,
          __nv_bfloat16* __restrict__ hhi, __nv_bfloat16* __restrict__ hlo,
          float* __restrict__ cOut,
          int M, int K, int KB)
{
    extern __shared__ char smem[];
    const uint32_t sbase = smem_u32(smem);

    const int tid = threadIdx.x;
    const int wid = tid >> 5, lid = tid & 31;
    const int wm = wid >> 2, wn = wid & 3;
    const int g = lid >> 2, t2 = (lid & 3) << 1;
    const int bm = blockIdx.x * 128;
    const int ny = blockIdx.y;
    const int Kc = KB >> 5;

    float acc[4][4][4];
    #pragma unroll
    for (int i = 0; i < 4; i++)
        #pragma unroll
        for (int j = 0; j < 4; j++)
            #pragma unroll
            for (int q = 0; q < 4; q++) acc[i][j][q] = 0.f;

    float4 aReg[4];

    auto issueB = [&](int ch, int s) {
        #pragma unroll
        for (int i = 0; i < 4; i++) {
            int e   = tid + i * 256;
            int mat = e >> 9;
            int rem = e & 511;
            int row = rem >> 2, cq = rem & 3;
            const __nv_bfloat16* srcm = mat ? Blo : Bhi;
            const __nv_bfloat16* src  = srcm + (size_t)(ny * 128 + row) * KB
                                             + ch * 32 + cq * 8;
            uint32_t dst = sbase + s * STAGE_B + (2 + mat) * MAT_B
                         + row * ST_ROW + cq * 16;
            CP_ASYNC16(dst, src);
        }
    };
    auto ldA = [&](int ch) {
        #pragma unroll
        for (int i = 0; i < 4; i++) {
            int e = tid + i * 256;
            int row = e >> 3, kq = e & 7;
            int k = ch * 32 + kq * 4;
            float4 v = make_float4(0.f, 0.f, 0.f, 0.f);
            if (bm + row < M && k < K)
                v = *(const float4*)(A + (size_t)(bm + row) * K + k);
            aReg[i] = v;
        }
    };
    auto stA = [&](int s) {
        char* base = smem + s * STAGE_B;
        #pragma unroll
        for (int i = 0; i < 4; i++) {
            int e = tid + i * 256;
            int row = e >> 3, kq = e & 7;
            float4 v = aReg[i];
            __nv_bfloat16 h0, l0, h1, l1, h2, l2, h3, l3;
            split_bf16(v.x, &h0, &l0); split_bf16(v.y, &h1, &l1);
            split_bf16(v.z, &h2, &l2); split_bf16(v.w, &h3, &l3);
            uint2 hv = make_uint2(pack_bf(h0, h1), pack_bf(h2, h3));
            uint2 lv = make_uint2(pack_bf(l0, l1), pack_bf(l2, l3));
            *(uint2*)(base + row * ST_ROW + kq * 8)         = hv;
            *(uint2*)(base + MAT_B + row * ST_ROW + kq * 8) = lv;
        }
    };
    auto compute = [&](int s) {
        const char* base = smem + s * STAGE_B;
        const char* Ah = base,             *Al = base + MAT_B;
        const char* Bh = base + 2 * MAT_B, *Bl = base + 3 * MAT_B;
        #pragma unroll
        for (int kk = 0; kk < 2; kk++) {
            const int kbyte = (kk * 16 + t2) * 2;
            uint32_t ah[4][4], al[4][4], bh[4][2], bl[4][2];
            #pragma unroll
            for (int am = 0; am < 4; am++) {
                int r = wm * 64 + am * 16 + g;
                ah[am][0] = *(const uint32_t*)(Ah + r * ST_ROW + kbyte);
                ah[am][1] = *(const uint32_t*)(Ah + (r + 8) * ST_ROW + kbyte);
                ah[am][2] = *(const uint32_t*)(Ah + r * ST_ROW + kbyte + 16);
                ah[am][3] = *(const uint32_t*)(Ah + (r + 8) * ST_ROW + kbyte + 16);
                al[am][0] = *(const uint32_t*)(Al + r * ST_ROW + kbyte);
                al[am][1] = *(const uint32_t*)(Al + (r + 8) * ST_ROW + kbyte);
                al[am][2] = *(const uint32_t*)(Al + r * ST_ROW + kbyte + 16);
                al[am][3] = *(const uint32_t*)(Al + (r + 8) * ST_ROW + kbyte + 16);
            }
            #pragma unroll
            for (int an = 0; an < 4; an++) {
                int n = wn * 32 + an * 8 + g;
                bh[an][0] = *(const uint32_t*)(Bh + n * ST_ROW + kbyte);
                bh[an][1] = *(const uint32_t*)(Bh + n * ST_ROW + kbyte + 16);
                bl[an][0] = *(const uint32_t*)(Bl + n * ST_ROW + kbyte);
                bl[an][1] = *(const uint32_t*)(Bl + n * ST_ROW + kbyte + 16);
            }
            #pragma unroll
            for (int am = 0; am < 4; am++)
                #pragma unroll
                for (int an = 0; an < 4; an++) {
                    MMA16816(acc[am][an], ah[am], bh[an]);
                    MMA16816(acc[am][an], ah[am], bl[an]);
                    MMA16816(acc[am][an], al[am], bh[an]);
                }
        }
    };

    issueB(0, 0); CP_COMMIT();
    ldA(0); stA(0);
    for (int ch = 0; ch < Kc; ch++) {
        const int s = ch & 1, nsg = s ^ 1;
        const bool more = (ch + 1 < Kc);
        if (more) { issueB(ch + 1, nsg); ldA(ch + 1); }
        CP_COMMIT();
        CP_WAIT1();
        __syncthreads();
        compute(s);
        if (more) stA(nsg);
    }

    // epilogue
    #pragma unroll
    for (int am = 0; am < 4; am++) {
        int r0 = bm + wm * 64 + am * 16 + g;
        #pragma unroll
        for (int an = 0; an < 4; an++) {
            int c  = wn * 32 + an * 8 + t2;
            float b0 = bias[ny * 128 + c], b1 = bias[ny * 128 + c + 1];
            float v00 = acc[am][an][0] + b0, v01 = acc[am][an][1] + b1;
            float v10 = acc[am][an][2] + b0, v11 = acc[am][an][3] + b1;
            if (ny == 0) {
                __nv_bfloat16 h0, l0, h1, l1;
                if (r0 < M) {
                    split_bf16(v00, &h0, &l0); split_bf16(v01, &h1, &l1);
                    *(uint32_t*)(hhi + (size_t)r0 * Hc + c) = pack_bf(h0, h1);
                    *(uint32_t*)(hlo + (size_t)r0 * Hc + c) = pack_bf(l0, l1);
                }
                if (r0 + 8 < M) {
                    split_bf16(v10, &h0, &l0); split_bf16(v11, &h1, &l1);
                    *(uint32_t*)(hhi + (size_t)(r0 + 8) * Hc + c) = pack_bf(h0, h1);
                    *(uint32_t*)(hlo + (size_t)(r0 + 8) * Hc + c) = pack_bf(l0, l1);
                }
            } else {
                if (r0 < M)
                    *(float2*)(cOut + (size_t)r0 * Hc + c) = make_float2(v00, v01);
                if (r0 + 8 < M)
                    *(float2*)(cOut + (size_t)(r0 + 8) * Hc + c) = make_float2(v10, v11);
            }
        }
    }
}

// --------------------------- fused level kernel -----------------------------
// gates = [h_l|h_r] @ WstPerm + bPerm; cell fused in epilogue.
// CTA tile 128 x 160 (32 units x 5 gates). A = h hi/lo bf16 via cp.async.
#define LVL_AROW   80
#define LVL_A_MAT  10240                   // 128*80
#define LVL_B_MAT  12800                   // 160*80
#define LVL_STAGE  46080
#define LVL_SMEM   (3 * LVL_STAGE)         // 138240
#define GSM_STRIDE 168

__global__ void __launch_bounds__(256, 1)
gemm_level(const __nv_bfloat16* __restrict__ Ahi, const __nv_bfloat16* __restrict__ Alo,
           const __nv_bfloat16* __restrict__ Bhi, const __nv_bfloat16* __restrict__ Blo,
           const float* __restrict__ biasp,
           const float* __restrict__ c_prev,
           __nv_bfloat16* __restrict__ hhi, __nv_bfloat16* __restrict__ hlo,
           float* __restrict__ cOut, float* __restrict__ hf_out,
           int M)
{
    extern __shared__ char smem[];
    const uint32_t sbase = smem_u32(smem);

    const int tid = threadIdx.x;
    const int wid = tid >> 5, lid = tid & 31;
    const int wm = wid >> 2, wn = wid & 3;          // 2 x 4 warps
    const int g = lid >> 2, t2 = (lid & 3) << 1;
    const int bm = blockIdx.x * 128;
    const int ny = blockIdx.y;                      // 0..3
    const int Kc = 8;                               // K = 256

    float acc[4][5][4];
    #pragma unroll
    for (int i = 0; i < 4; i++)
        #pragma unroll
        for (int j = 0; j < 5; j++)
            #pragma unroll
            for (int q = 0; q < 4; q++) acc[i][j][q] = 0.f;

    auto issue = [&](int ch) {
        const uint32_t st = sbase + (ch % 3) * LVL_STAGE;
        #pragma unroll
        for (int i = 0; i < 9; i++) {
            int e = tid + i * 256;
            const __nv_bfloat16* src;
            uint32_t dst;
            if (e < 1024) {                          // A hi/lo: 128 rows x 64B
                int mat = e >> 9;
                int r = (e & 511) >> 2, q = e & 3;
                src = (mat ? Alo : Ahi) + (size_t)(bm + r) * 256 + ch * 32 + q * 8;
                dst = st + mat * LVL_A_MAT + r * LVL_AROW + q * 16;
            } else {                                 // B hi/lo: 160 rows x 64B
                int e2 = e - 1024;
                int mat = e2 >= 640;
                int r = (mat ? e2 - 640 : e2) >> 2, q = e2 & 3;
                src = (mat ? Blo : Bhi) + (size_t)(ny * 160 + r) * 256 + ch * 32 + q * 8;
                dst = st + 2 * LVL_A_MAT + mat * LVL_B_MAT + r * LVL_AROW + q * 16;
            }
            CP_ASYNC16(dst, src);
        }
    };

    auto compute = [&](int s) {
        const char* base = smem + s * LVL_STAGE;
        const char* Ah = base,                 *Al = base + LVL_A_MAT;
        const char* Bh = base + 2 * LVL_A_MAT, *Bl = Bh + LVL_B_MAT;
        #pragma unroll
        for (int kk = 0; kk < 2; kk++) {
            const int kbyte = (kk * 16 + t2) * 2;
            uint32_t ah[4][4], al[4][4], bh[5][2], bl[5][2];
            #pragma unroll
            for (int am = 0; am < 4; am++) {
                int r = wm * 64 + am * 16 + g;
                ah[am][0] = *(const uint32_t*)(Ah + r * LVL_AROW + kbyte);
                ah[am][1] = *(const uint32_t*)(Ah + (r + 8) * LVL_AROW + kbyte);
                ah[am][2] = *(const uint32_t*)(Ah + r * LVL_AROW + kbyte + 16);
                ah[am][3] = *(const uint32_t*)(Ah + (r + 8) * LVL_AROW + kbyte + 16);
                al[am][0] = *(const uint32_t*)(Al + r * LVL_AROW + kbyte);
                al[am][1] = *(const uint32_t*)(Al + (r + 8) * LVL_AROW + kbyte);
                al[am][2] = *(const uint32_t*)(Al + r * LVL_AROW + kbyte + 16);
                al[am][3] = *(const uint32_t*)(Al + (r + 8) * LVL_AROW + kbyte + 16);
            }
            #pragma unroll
            for (int an = 0; an < 5; an++) {
                int n = wn * 40 + an * 8 + g;
                bh[an][0] = *(const uint32_t*)(Bh + n * LVL_AROW + kbyte);
                bh[an][1] = *(const uint32_t*)(Bh + n * LVL_AROW + kbyte + 16);
                bl[an][0] = *(const uint32_t*)(Bl + n * LVL_AROW + kbyte);
                bl[an][1] = *(const uint32_t*)(Bl + n * LVL_AROW + kbyte + 16);
            }
            #pragma unroll
            for (int am = 0; am < 4; am++)
                #pragma unroll
                for (int an = 0; an < 5; an++) {
                    MMA16816(acc[am][an], ah[am], bh[an]);
                    MMA16816(acc[am][an], ah[am], bl[an]);
                    MMA16816(acc[am][an], al[am], bh[an]);
                }
        }
    };

    // 3-stage pipeline
    issue(0); CP_COMMIT();
    issue(1); CP_COMMIT();
    for (int ch = 0; ch < Kc; ch++) {
        CP_WAIT1();
        __syncthreads();           // stage ch visible; all warps done with stage (ch+2)%3
        if (ch + 2 < Kc) issue(ch + 2);
        CP_COMMIT();
        compute(ch % 3);
    }
    CP_WAIT0();
    __syncthreads();

    // ---- epilogue: acc -> gate smem -> fused cell ----
    float* gsm = (float*)smem;                      // 128 x 168 f32 = 86016 B
    #pragma unroll
    for (int am = 0; am < 4; am++) {
        int r = wm * 64 + am * 16 + g;
        #pragma unroll
        for (int an = 0; an < 5; an++) {
            int c = wn * 40 + an * 8 + t2;
            float b0 = biasp[ny * 160 + c], b1 = biasp[ny * 160 + c + 1];
            gsm[r * GSM_STRIDE + c]           = acc[am][an][0] + b0;
            gsm[r * GSM_STRIDE + c + 1]       = acc[am][an][1] + b1;
            gsm[(r + 8) * GSM_STRIDE + c]     = acc[am][an][2] + b0;
            gsm[(r + 8) * GSM_STRIDE + c + 1] = acc[am][an][3] + b1;
        }
    }
    __syncthreads();

    const int u  = tid & 31;                        // unit within tile
    const int r0 = tid >> 5;                        // 0..7
    const int ug = ny * 32 + u;                     // global hidden unit
    #pragma unroll
    for (int it = 0; it < 16; it++) {
        int row = r0 + it * 8;
        int gr  = bm + row;
        if (gr >= M) break;
        const float* gp = gsm + row * GSM_STRIDE;
        float gi = sigf(gp[u]);
        float fl = sigf(gp[32 + u]);
        float fr = sigf(gp[64 + u]);
        float go = sigf(gp[96 + u]);
        float gg = tanhf(gp[128 + u]);
        float cl = c_prev[(size_t)gr * 256 + ug];
        float cr = c_prev[(size_t)gr * 256 + 128 + ug];
        float cc = fl * cl + fr * cr + gi * gg;
        float hh = go * tanhf(cc);
        cOut[(size_t)gr * Hc + ug] = cc;
        if (hf_out) {
            hf_out[(size_t)gr * Hc + ug] = hh;
        } else {
            __nv_bfloat16 hb, lb;
            split_bf16(hh, &hb, &lb);
            hhi[(size_t)gr * Hc + ug] = hb;
            hlo[(size_t)gr * Hc + ug] = lb;
        }
    }
}

// --------------------------------- launch ----------------------------------
extern "C" void kernel_launch(void* const* d_in, const int* in_sizes, int n_in,
                              void* d_out, int out_size)
{
    const float* x      = (const float*)d_in[0];
    const float* W_leaf = (const float*)d_in[1];
    const float* b_leaf = (const float*)d_in[2];
    const float* W_l    = (const float*)d_in[3];
    const float* W_r    = (const float*)d_in[4];
    const float* bg     = (const float*)d_in[5];

    const int twoH = in_sizes[2];            // 256
    const int H    = twoH / 2;               // 128
    const int D    = in_sizes[1] / twoH;     // 300
    const int BL   = in_sizes[0] / D;        // 32768
    const int B    = out_size / H;           // 8
    const int L    = BL / B;                 // 4096
    int levels = 0;
    for (int t = L; t > 1; t >>= 1) levels++;

    __nv_bfloat16 *hhiA, *hloA, *hhiB, *hloB, *Wt_hi, *Wt_lo, *Wlf_hi, *Wlf_lo;
    float *cA, *cB, *bperm;
    cudaGetSymbolAddress((void**)&hhiA,   g_hhiA);
    cudaGetSymbolAddress((void**)&hloA,   g_hloA);
    cudaGetSymbolAddress((void**)&hhiB,   g_hhiB);
    cudaGetSymbolAddress((void**)&hloB,   g_hloB);
    cudaGetSymbolAddress((void**)&cA,     g_cA);
    cudaGetSymbolAddress((void**)&cB,     g_cB);
    cudaGetSymbolAddress((void**)&bperm,  g_bperm);
    cudaGetSymbolAddress((void**)&Wt_hi,  g_Wt_hi);
    cudaGetSymbolAddress((void**)&Wt_lo,  g_Wt_lo);
    cudaGetSymbolAddress((void**)&Wlf_hi, g_WlfT_hi);
    cudaGetSymbolAddress((void**)&Wlf_lo, g_WlfT_lo);

    cudaFuncSetAttribute(gemm_leaf,  cudaFuncAttributeMaxDynamicSharedMemorySize, SMEM_LEAF);
    cudaFuncSetAttribute(gemm_level, cudaFuncAttributeMaxDynamicSharedMemorySize, LVL_SMEM);

    // 1) weight prep
    prep_wst  <<<(NGATE * 256 + 255) / 256, 256>>>(W_l, W_r, bg, Wt_hi, Wt_lo, bperm);
    prep_wleaf<<<(256 * KB_LEAF + 255) / 256, 256>>>(W_leaf, Wlf_hi, Wlf_lo);

    // 2) leaf GEMM -> h (hi/lo bf16) | c (f32)
    {
        dim3 grid((BL + 127) / 128, 2);
        gemm_leaf<<<grid, 256, SMEM_LEAF>>>(x, Wlf_hi, Wlf_lo, b_leaf,
                                            hhiA, hloA, cA, BL, D, KB_LEAF);
    }

    // 3) fused reduction levels (ping-pong)
    __nv_bfloat16 *sh_hi = hhiA, *sh_lo = hloA, *dh_hi = hhiB, *dh_lo = hloB;
    float *sc = cA, *dc = cB;
    int n = L;
    for (int lvl = 0; lvl < levels; lvl++) {
        n >>= 1;
        int M = B * n;
        bool last = (lvl == levels - 1);

        dim3 grid((M + 127) / 128, 4);
        gemm_level<<<grid, 256, LVL_SMEM>>>(sh_hi, sh_lo, Wt_hi, Wt_lo, bperm,
                                            sc, dh_hi, dh_lo, dc,
                                            last ? (float*)d_out : nullptr, M);

        __nv_bfloat16* t;
        t = sh_hi; sh_hi = dh_hi; dh_hi = t;
        t = sh_lo; sh_lo = dh_lo; dh_lo = t;
        float* tc = sc; sc = dc; dc = tc;
    }
}

// round 5
// speedup vs baseline: 1.2965x; 1.2965x over previous
#include <cuda_runtime.h>
#include <cuda_bf16.h>
#include <math.h>
#include <stdint.h>

// ---------------------------------------------------------------------------
// TreeLSTM on GB300, mma.sync bf16x3 (tcgen05 feature-gated off on this
// harness's compute_103 target).
// R5: ldmatrix fragment loads (swizzled 128B rows), h carried as bf16 hi/lo so
// level GEMMs are pure cp.async, BK=64 double buffer, fused SIMT kernel for
// tiny levels.  D = Ah*Bh + Ah*Bl + Al*Bh, fp32 accumulators.
// ---------------------------------------------------------------------------

#define Hc      128
#define MAXBL   32768
#define NGATE   640
#define KB_LEAF 320

__device__ __align__(128) __nv_bfloat16 g_hhiA[MAXBL * Hc];
__device__ __align__(128) __nv_bfloat16 g_hloA[MAXBL * Hc];
__device__ __align__(128) __nv_bfloat16 g_hhiB[(MAXBL / 2) * Hc];
__device__ __align__(128) __nv_bfloat16 g_hloB[(MAXBL / 2) * Hc];
__device__ float g_cA[MAXBL * Hc];
__device__ float g_cB[(MAXBL / 2) * Hc];
__device__ float g_gates[(MAXBL / 2) * NGATE];
__device__ __align__(128) __nv_bfloat16 g_Wt_hi[NGATE * 256];     // [640,256] K-major
__device__ __align__(128) __nv_bfloat16 g_Wt_lo[NGATE * 256];
__device__ float g_Wstf[256 * NGATE];                             // [256,640] fp32
__device__ __align__(128) __nv_bfloat16 g_WlfT_hi[256 * KB_LEAF]; // [256,320]
__device__ __align__(128) __nv_bfloat16 g_WlfT_lo[256 * KB_LEAF];

// ------------------------------- helpers -----------------------------------
__device__ __forceinline__ uint32_t smem_u32(const void* p) {
    uint32_t a;
    asm("{ .reg .u64 t; cvta.to.shared.u64 t, %1; cvt.u32.u64 %0, t; }"
        : "=r"(a) : "l"(p));
    return a;
}
#define CP_ASYNC16(dst, src) \
    asm volatile("cp.async.cg.shared.global [%0], [%1], 16;" \
                 :: "r"(dst), "l"(src) : "memory")
#define CP_COMMIT() asm volatile("cp.async.commit_group;" ::: "memory")
#define CP_WAIT1()  asm volatile("cp.async.wait_group 1;"  ::: "memory")
#define CP_WAIT0()  asm volatile("cp.async.wait_group 0;"  ::: "memory")

#define MMA16816(c, a, b)                                                      \
    asm volatile("mma.sync.aligned.m16n8k16.row.col.f32.bf16.bf16.f32 "       \
        "{%0,%1,%2,%3},{%4,%5,%6,%7},{%8,%9},{%0,%1,%2,%3};"                  \
        : "+f"((c)[0]), "+f"((c)[1]), "+f"((c)[2]), "+f"((c)[3])              \
        : "r"((a)[0]), "r"((a)[1]), "r"((a)[2]), "r"((a)[3]),                 \
          "r"((b)[0]), "r"((b)[1]))

__device__ __forceinline__ void ldsm4(uint32_t a, uint32_t& r0, uint32_t& r1,
                                      uint32_t& r2, uint32_t& r3) {
    asm volatile("ldmatrix.sync.aligned.m8n8.x4.shared.b16 {%0,%1,%2,%3}, [%4];"
                 : "=r"(r0), "=r"(r1), "=r"(r2), "=r"(r3) : "r"(a));
}

__device__ __forceinline__ void split_bf16(float w, __nv_bfloat16* hi, __nv_bfloat16* lo) {
    __nv_bfloat16 h = __float2bfloat16(w);
    *hi = h;
    *lo = __float2bfloat16(w - __bfloat162float(h));
}
__device__ __forceinline__ uint32_t pack_bf(__nv_bfloat16 a, __nv_bfloat16 b) {
    __nv_bfloat162 t{a, b};
    return *(uint32_t*)&t;
}
__device__ __forceinline__ float sigf(float x) { return 1.0f / (1.0f + expf(-x)); }

// Stage layout: A_hi | A_lo | B_hi | B_lo, each 128 rows x 128 bytes, xor-swizzled.
#define TILE_B 16384
#define STAGE  65536

// Shared mainloop compute: 4 k-steps of 16, 48 MMAs each, ldmatrix loads.
__device__ __forceinline__ void stage_compute(uint32_t st, int wm, int wn, int lane,
                                              float (*acc)[4][4])
{
    const int ts = lane >> 3, rs = lane & 7;
    const uint32_t Ah = st, Al = st + TILE_B, Bh = st + 2 * TILE_B, Bl = st + 3 * TILE_B;
    const int arow = wm * 64 + ((ts & 1) << 3) + rs;   // + am*16
    const int ach  = ts >> 1;                          // + kk*2
    const int brow = wn * 32 + ((ts >> 1) << 3) + rs;  // + j*16
    const int bch  = ts & 1;
    #pragma unroll
    for (int kk = 0; kk < 4; kk++) {
        uint32_t ah[4][4], al[4][4], bh[4][2], bl[4][2];
        #pragma unroll
        for (int am = 0; am < 4; am++) {
            uint32_t off = (uint32_t)((arow + am * 16) * 128)
                         + (((uint32_t)((kk * 2 + ach) ^ rs)) << 4);
            ldsm4(Ah + off, ah[am][0], ah[am][1], ah[am][2], ah[am][3]);
            ldsm4(Al + off, al[am][0], al[am][1], al[am][2], al[am][3]);
        }
        #pragma unroll
        for (int j = 0; j < 2; j++) {
            uint32_t off = (uint32_t)((brow + j * 16) * 128)
                         + (((uint32_t)((kk * 2 + bch) ^ rs)) << 4);
            ldsm4(Bh + off, bh[2*j][0], bh[2*j][1], bh[2*j+1][0], bh[2*j+1][1]);
            ldsm4(Bl + off, bl[2*j][0], bl[2*j][1], bl[2*j+1][0], bl[2*j+1][1]);
        }
        #pragma unroll
        for (int am = 0; am < 4; am++)
            #pragma unroll
            for (int an = 0; an < 4; an++) {
                MMA16816(acc[am][an], ah[am], bh[an]);
                MMA16816(acc[am][an], ah[am], bl[an]);
                MMA16816(acc[am][an], al[am], bh[an]);
            }
    }
}

// ------------------------ weight prep (once/replay) ------------------------
__global__ void prep_wst(const float* __restrict__ Wl, const float* __restrict__ Wr,
                         __nv_bfloat16* __restrict__ hi, __nv_bfloat16* __restrict__ lo,
                         float* __restrict__ Wf)
{
    int idx = blockIdx.x * blockDim.x + threadIdx.x;
    if (idx >= NGATE * 256) return;
    int n = idx >> 8, k = idx & 255;
    float w = (k < 128) ? Wl[k * NGATE + n] : Wr[(k - 128) * NGATE + n];
    split_bf16(w, &hi[idx], &lo[idx]);
    Wf[k * NGATE + n] = w;
}

__global__ void prep_wleaf(const float* __restrict__ W,
                           __nv_bfloat16* __restrict__ hi, __nv_bfloat16* __restrict__ lo)
{
    int idx = blockIdx.x * blockDim.x + threadIdx.x;
    if (idx >= 256 * KB_LEAF) return;
    int n = idx / KB_LEAF, k = idx % KB_LEAF;
    float w = (k < 300) ? W[k * 256 + n] : 0.0f;
    split_bf16(w, &hi[idx], &lo[idx]);
}

// ------------------------------ leaf GEMM -----------------------------------
// hc = x @ W_leaf + b_leaf.  ny==0 -> h (hi/lo bf16); ny==1 -> c (f32).
// A fp32 converted in-kernel; B pre-split via cp.async. BK=64, 2 stages.
#define SMEM_REQ (2 * STAGE + 128)

__global__ void __launch_bounds__(256, 1)
gemm_leaf(const float* __restrict__ A,
          const __nv_bfloat16* __restrict__ Bhi, const __nv_bfloat16* __restrict__ Blo,
          const float* __restrict__ bias,
          __nv_bfloat16* __restrict__ hhi, __nv_bfloat16* __restrict__ hlo,
          float* __restrict__ cOut, int M, int K, int KB)
{
    extern __shared__ char smem[];
    const uint32_t sb    = smem_u32(smem);
    const uint32_t sbase = (sb + 127) & ~127u;
    char* const tb = smem + (sbase - sb);

    const int tid = threadIdx.x;
    const int wid = tid >> 5, lane = tid & 31;
    const int wm = wid >> 2, wn = wid & 3;
    const int g = lane >> 2, t2 = (lane & 3) << 1;
    const int bm = blockIdx.x * 128;
    const int ny = blockIdx.y;
    const int Kc = KB >> 6;              // 5

    float acc[4][4][4];
    #pragma unroll
    for (int i = 0; i < 4; i++)
        #pragma unroll
        for (int j = 0; j < 4; j++)
            #pragma unroll
            for (int q = 0; q < 4; q++) acc[i][j][q] = 0.f;

    float4 aReg[8];

    auto issueB = [&](int ch) {
        uint32_t st = sbase + (ch & 1) * STAGE + 2 * TILE_B;
        #pragma unroll
        for (int i = 0; i < 8; i++) {
            int e = tid + i * 256;
            int mat = e >> 10;
            int rem = e & 1023;
            int row = rem >> 3, chunk = rem & 7;
            const __nv_bfloat16* src = (mat ? Blo : Bhi)
                + (size_t)(ny * 128 + row) * KB + ch * 64 + chunk * 8;
            uint32_t dst = st + mat * TILE_B + row * 128 + ((chunk ^ (row & 7)) << 4);
            CP_ASYNC16(dst, src);
        }
    };
    auto ldA = [&](int ch) {
        #pragma unroll
        for (int i = 0; i < 8; i++) {
            int f = tid + i * 256;
            int row = f >> 4, k4 = (f & 15) << 2;
            int k = ch * 64 + k4;
            float4 v = make_float4(0.f, 0.f, 0.f, 0.f);
            if (k < K) v = *(const float4*)(A + (size_t)(bm + row) * K + k);
            aReg[i] = v;
        }
    };
    auto stA = [&](int s) {
        char* st = tb + s * STAGE;
        #pragma unroll
        for (int i = 0; i < 8; i++) {
            int f = tid + i * 256;
            int row = f >> 4, k4 = (f & 15) << 2;
            int chunk = k4 >> 3, half = (k4 >> 2) & 1;
            uint32_t off = row * 128 + ((chunk ^ (row & 7)) << 4) + half * 8;
            float4 v = aReg[i];
            __nv_bfloat16 h0, l0, h1, l1, h2, l2, h3, l3;
            split_bf16(v.x, &h0, &l0); split_bf16(v.y, &h1, &l1);
            split_bf16(v.z, &h2, &l2); split_bf16(v.w, &h3, &l3);
            *(uint2*)(st + off)          = make_uint2(pack_bf(h0, h1), pack_bf(h2, h3));
            *(uint2*)(st + TILE_B + off) = make_uint2(pack_bf(l0, l1), pack_bf(l2, l3));
        }
    };

    issueB(0); CP_COMMIT();
    ldA(0); stA(0);
    if (Kc > 1) { issueB(1); CP_COMMIT(); ldA(1); }
    for (int ch = 0; ch < Kc; ch++) {
        if (ch + 1 < Kc) CP_WAIT1(); else CP_WAIT0();
        __syncthreads();                       // stage ch fully ready for all
        stage_compute(sbase + (ch & 1) * STAGE, wm, wn, lane, acc);
        if (ch + 1 < Kc) stA((ch + 1) & 1);    // A regs (ch+1) -> other stage
        __syncthreads();                       // all done reading stage ch
        if (ch + 2 < Kc) { issueB(ch + 2); CP_COMMIT(); ldA(ch + 2); }
    }

    // epilogue (M divisible by 128 -> no guards)
    #pragma unroll
    for (int am = 0; am < 4; am++) {
        int r0 = bm + wm * 64 + am * 16 + g;
        #pragma unroll
        for (int an = 0; an < 4; an++) {
            int c  = wn * 32 + an * 8 + t2;
            float b0 = bias[ny * 128 + c], b1 = bias[ny * 128 + c + 1];
            float v00 = acc[am][an][0] + b0, v01 = acc[am][an][1] + b1;
            float v10 = acc[am][an][2] + b0, v11 = acc[am][an][3] + b1;
            if (ny == 0) {
                __nv_bfloat16 h0, l0, h1, l1;
                split_bf16(v00, &h0, &l0); split_bf16(v01, &h1, &l1);
                *(uint32_t*)(hhi + (size_t)r0 * Hc + c) = pack_bf(h0, h1);
                *(uint32_t*)(hlo + (size_t)r0 * Hc + c) = pack_bf(l0, l1);
                split_bf16(v10, &h0, &l0); split_bf16(v11, &h1, &l1);
                *(uint32_t*)(hhi + (size_t)(r0 + 8) * Hc + c) = pack_bf(h0, h1);
                *(uint32_t*)(hlo + (size_t)(r0 + 8) * Hc + c) = pack_bf(l0, l1);
            } else {
                *(float2*)(cOut + (size_t)r0 * Hc + c)       = make_float2(v00, v01);
                *(float2*)(cOut + (size_t)(r0 + 8) * Hc + c) = make_float2(v10, v11);
            }
        }
    }
}

// ------------------------------ level GEMM ----------------------------------
// gates[M,640] = h_pairs[M,256](hi/lo bf16) @ Wst + b.  All cp.async. Kc=4.
__global__ void __launch_bounds__(256, 1)
gemm_level(const __nv_bfloat16* __restrict__ Ahi, const __nv_bfloat16* __restrict__ Alo,
           const __nv_bfloat16* __restrict__ Bhi, const __nv_bfloat16* __restrict__ Blo,
           const float* __restrict__ bias, float* __restrict__ gates, int M)
{
    extern __shared__ char smem[];
    const uint32_t sb    = smem_u32(smem);
    const uint32_t sbase = (sb + 127) & ~127u;

    const int tid = threadIdx.x;
    const int wid = tid >> 5, lane = tid & 31;
    const int wm = wid >> 2, wn = wid & 3;
    const int g = lane >> 2, t2 = (lane & 3) << 1;
    const int bm = blockIdx.x * 128;
    const int ny = blockIdx.y;
    const int Kc = 4;                    // K = 256

    float acc[4][4][4];
    #pragma unroll
    for (int i = 0; i < 4; i++)
        #pragma unroll
        for (int j = 0; j < 4; j++)
            #pragma unroll
            for (int q = 0; q < 4; q++) acc[i][j][q] = 0.f;

    auto issue = [&](int ch) {
        uint32_t st = sbase + (ch & 1) * STAGE;
        #pragma unroll
        for (int i = 0; i < 8; i++) {    // A hi/lo
            int e = tid + i * 256;
            int mat = e >> 10;
            int rem = e & 1023;
            int row = rem >> 3, chunk = rem & 7;
            const __nv_bfloat16* src = (mat ? Alo : Ahi)
                + (size_t)(bm + row) * 256 + ch * 64 + chunk * 8;
            uint32_t dst = st + mat * TILE_B + row * 128 + ((chunk ^ (row & 7)) << 4);
            CP_ASYNC16(dst, src);
        }
        #pragma unroll
        for (int i = 0; i < 8; i++) {    // B hi/lo
            int e = tid + i * 256;
            int mat = e >> 10;
            int rem = e & 1023;
            int row = rem >> 3, chunk = rem & 7;
            const __nv_bfloat16* src = (mat ? Blo : Bhi)
                + (size_t)(ny * 128 + row) * 256 + ch * 64 + chunk * 8;
            uint32_t dst = st + 2 * TILE_B + mat * TILE_B + row * 128
                         + ((chunk ^ (row & 7)) << 4);
            CP_ASYNC16(dst, src);
        }
    };

    issue(0); CP_COMMIT();
    issue(1); CP_COMMIT();
    for (int ch = 0; ch < Kc; ch++) {
        if (ch + 1 < Kc) CP_WAIT1(); else CP_WAIT0();
        __syncthreads();
        stage_compute(sbase + (ch & 1) * STAGE, wm, wn, lane, acc);
        __syncthreads();
        if (ch + 2 < Kc) { issue(ch + 2); CP_COMMIT(); }
    }

    #pragma unroll
    for (int am = 0; am < 4; am++) {
        int r0 = bm + wm * 64 + am * 16 + g;
        #pragma unroll
        for (int an = 0; an < 4; an++) {
            int c  = wn * 32 + an * 8 + t2;
            int gc = ny * 128 + c;
            float b0 = bias[gc], b1 = bias[gc + 1];
            *(float2*)(gates + (size_t)r0 * NGATE + gc)
                = make_float2(acc[am][an][0] + b0, acc[am][an][1] + b1);
            *(float2*)(gates + (size_t)(r0 + 8) * NGATE + gc)
                = make_float2(acc[am][an][2] + b0, acc[am][an][3] + b1);
        }
    }
}

// ------------------------------- LSTM cell ----------------------------------
__global__ void lstm_cell4(const float* __restrict__ gates,
                           const float* __restrict__ c_prev,
                           __nv_bfloat16* __restrict__ hhi, __nv_bfloat16* __restrict__ hlo,
                           float* __restrict__ c_out, int M)
{
    int idx = blockIdx.x * blockDim.x + threadIdx.x;
    if (idx >= M * 32) return;
    int r = idx >> 5, j = (idx & 31) << 2;
    const float* g = gates + (size_t)r * NGATE;
    float4 i4  = *(const float4*)(g + j);
    float4 fl4 = *(const float4*)(g + 128 + j);
    float4 fr4 = *(const float4*)(g + 256 + j);
    float4 o4  = *(const float4*)(g + 384 + j);
    float4 g4  = *(const float4*)(g + 512 + j);
    const float* cp = c_prev + (size_t)r * 256;
    float4 cl4 = *(const float4*)(cp + j);
    float4 cr4 = *(const float4*)(cp + 128 + j);
    float4 c, h;
#define CEL(X) { float ii = sigf(i4.X), fl = sigf(fl4.X), fr = sigf(fr4.X);      \
                 float oo = sigf(o4.X), gg = tanhf(g4.X);                        \
                 float cc = fl * cl4.X + fr * cr4.X + ii * gg;                   \
                 c.X = cc; h.X = oo * tanhf(cc); }
    CEL(x) CEL(y) CEL(z) CEL(w)
#undef CEL
    *(float4*)(c_out + (size_t)r * Hc + j) = c;
    __nv_bfloat16 b0, l0, b1, l1, b2, l2, b3, l3;
    split_bf16(h.x, &b0, &l0); split_bf16(h.y, &b1, &l1);
    split_bf16(h.z, &b2, &l2); split_bf16(h.w, &b3, &l3);
    *(uint2*)(hhi + (size_t)r * Hc + j) = make_uint2(pack_bf(b0, b1), pack_bf(b2, b3));
    *(uint2*)(hlo + (size_t)r * Hc + j) = make_uint2(pack_bf(l0, l1), pack_bf(l2, l3));
}

// --------------------- fused tiny-level kernel (M <= 128) -------------------
#define RSM 4
__global__ void __launch_bounds__(640)
level_small(const __nv_bfloat16* __restrict__ Ahi, const __nv_bfloat16* __restrict__ Alo,
            const float* __restrict__ Wf, const float* __restrict__ bg,
            const float* __restrict__ c_prev,
            __nv_bfloat16* __restrict__ hhi_o, __nv_bfloat16* __restrict__ hlo_o,
            float* __restrict__ c_out, float* __restrict__ hf_out, int M)
{
    __shared__ float hs[RSM][256];
    __shared__ float gs[RSM][NGATE];
    const int tid = threadIdx.x;
    const int r0 = blockIdx.x * RSM;

    for (int idx = tid; idx < RSM * 256; idx += 640) {
        int r = idx >> 8, k = idx & 255;
        int gr = r0 + r;
        float v = 0.f;
        if (gr < M)
            v = __bfloat162float(Ahi[(size_t)gr * 256 + k])
              + __bfloat162float(Alo[(size_t)gr * 256 + k]);
        hs[r][k] = v;
    }
    __syncthreads();

    {
        const int c = tid;                     // 640 cols, 640 threads
        float a0 = 0.f, a1 = 0.f, a2 = 0.f, a3 = 0.f;
        #pragma unroll 4
        for (int k = 0; k < 256; k++) {
            float w = Wf[k * NGATE + c];
            a0 += hs[0][k] * w; a1 += hs[1][k] * w;
            a2 += hs[2][k] * w; a3 += hs[3][k] * w;
        }
        float b = bg[c];
        gs[0][c] = a0 + b; gs[1][c] = a1 + b; gs[2][c] = a2 + b; gs[3][c] = a3 + b;
    }
    __syncthreads();

    if (tid < RSM * 128) {
        int r = tid >> 7, u = tid & 127;
        int gr = r0 + r;
        if (gr < M) {
            float gi = sigf(gs[r][u]);
            float fl = sigf(gs[r][128 + u]);
            float fr = sigf(gs[r][256 + u]);
            float go = sigf(gs[r][384 + u]);
            float gg = tanhf(gs[r][512 + u]);
            float cl = c_prev[(size_t)gr * 256 + u];
            float cr = c_prev[(size_t)gr * 256 + 128 + u];
            float cc = fl * cl + fr * cr + gi * gg;
            float hh = go * tanhf(cc);
            c_out[(size_t)gr * Hc + u] = cc;
            if (hf_out) {
                hf_out[(size_t)gr * Hc + u] = hh;
            } else {
                __nv_bfloat16 hb, lb;
                split_bf16(hh, &hb, &lb);
                hhi_o[(size_t)gr * Hc + u] = hb;
                hlo_o[(size_t)gr * Hc + u] = lb;
            }
        }
    }
}

// --------------------------------- launch -----------------------------------
extern "C" void kernel_launch(void* const* d_in, const int* in_sizes, int n_in,
                              void* d_out, int out_size)
{
    const float* x      = (const float*)d_in[0];
    const float* W_leaf = (const float*)d_in[1];
    const float* b_leaf = (const float*)d_in[2];
    const float* W_l    = (const float*)d_in[3];
    const float* W_r    = (const float*)d_in[4];
    const float* bg     = (const float*)d_in[5];

    const int twoH = in_sizes[2];            // 256
    const int H    = twoH / 2;               // 128
    const int D    = in_sizes[1] / twoH;     // 300
    const int BL   = in_sizes[0] / D;        // 32768
    const int B    = out_size / H;           // 8
    const int L    = BL / B;                 // 4096
    int levels = 0;
    for (int t = L; t > 1; t >>= 1) levels++;

    __nv_bfloat16 *hhiA, *hloA, *hhiB, *hloB, *Wt_hi, *Wt_lo, *Wlf_hi, *Wlf_lo;
    float *cA, *cB, *gates, *Wstf;
    cudaGetSymbolAddress((void**)&hhiA,   g_hhiA);
    cudaGetSymbolAddress((void**)&hloA,   g_hloA);
    cudaGetSymbolAddress((void**)&hhiB,   g_hhiB);
    cudaGetSymbolAddress((void**)&hloB,   g_hloB);
    cudaGetSymbolAddress((void**)&cA,     g_cA);
    cudaGetSymbolAddress((void**)&cB,     g_cB);
    cudaGetSymbolAddress((void**)&gates,  g_gates);
    cudaGetSymbolAddress((void**)&Wstf,   g_Wstf);
    cudaGetSymbolAddress((void**)&Wt_hi,  g_Wt_hi);
    cudaGetSymbolAddress((void**)&Wt_lo,  g_Wt_lo);
    cudaGetSymbolAddress((void**)&Wlf_hi, g_WlfT_hi);
    cudaGetSymbolAddress((void**)&Wlf_lo, g_WlfT_lo);

    cudaFuncSetAttribute(gemm_leaf,  cudaFuncAttributeMaxDynamicSharedMemorySize, SMEM_REQ);
    cudaFuncSetAttribute(gemm_level, cudaFuncAttributeMaxDynamicSharedMemorySize, SMEM_REQ);

    // 1) weight prep
    prep_wst  <<<(NGATE * 256 + 255) / 256, 256>>>(W_l, W_r, Wt_hi, Wt_lo, Wstf);
    prep_wleaf<<<(256 * KB_LEAF + 255) / 256, 256>>>(W_leaf, Wlf_hi, Wlf_lo);

    // 2) leaf GEMM
    {
        dim3 grid(BL / 128, 2);
        gemm_leaf<<<grid, 256, SMEM_REQ>>>(x, Wlf_hi, Wlf_lo, b_leaf,
                                           hhiA, hloA, cA, BL, D, KB_LEAF);
    }

    // 3) reduction levels
    __nv_bfloat16 *sh_hi = hhiA, *sh_lo = hloA, *dh_hi = hhiB, *dh_lo = hloB;
    float *sc = cA, *dc = cB;
    int n = L;
    for (int lvl = 0; lvl < levels; lvl++) {
        n >>= 1;
        int M = B * n;
        bool last = (lvl == levels - 1);

        if (M >= 256) {
            dim3 grid(M / 128, 5);
            gemm_level<<<grid, 256, SMEM_REQ>>>(sh_hi, sh_lo, Wt_hi, Wt_lo, bg, gates, M);
            lstm_cell4<<<(M * 32 + 255) / 256, 256>>>(gates, sc, dh_hi, dh_lo, dc, M);
        } else {
            level_small<<<(M + RSM - 1) / RSM, 640>>>(sh_hi, sh_lo, Wstf, bg, sc,
                                                      dh_hi, dh_lo, dc,
                                                      last ? (float*)d_out : nullptr, M);
        }

        __nv_bfloat16* t;
        t = sh_hi; sh_hi = dh_hi; dh_hi = t;
        t = sh_lo; sh_lo = dh_lo; dh_lo = t;
        float* tc = sc; sc = dc; dc = tc;
    }
}